// round 5
// baseline (speedup 1.0000x reference)
#include <cuda_runtime.h>
#include <cstdint>

#define B_BAGS 16384

// Per-table exclusive prefix offsets (scratch, computed each launch).
__device__ int g_off[4][B_BAGS + 1];

// ---------------------------------------------------------------------------
// Scan kernel: one block per table, 1024 threads, 16 lens per thread.
// ---------------------------------------------------------------------------
__global__ void scan_kernel(const int* __restrict__ l0, const int* __restrict__ l1,
                            const int* __restrict__ l2, const int* __restrict__ l3) {
    const int* lens = (blockIdx.x == 0) ? l0 : (blockIdx.x == 1) ? l1
                    : (blockIdx.x == 2) ? l2 : l3;
    int* off = g_off[blockIdx.x];
    __shared__ int sh[1024];
    int t = threadIdx.x;
    int vals[16];
    int s = 0;
#pragma unroll
    for (int k = 0; k < 16; k++) {
        int v = lens[t * 16 + k];
        vals[k] = s;      // exclusive within chunk
        s += v;
    }
    sh[t] = s;
    __syncthreads();
    // Hillis-Steele inclusive scan over 1024 chunk sums
    for (int d = 1; d < 1024; d <<= 1) {
        int x = (t >= d) ? sh[t - d] : 0;
        __syncthreads();
        sh[t] += x;
        __syncthreads();
    }
    int excl = (t == 0) ? 0 : sh[t - 1];
#pragma unroll
    for (int k = 0; k < 16; k++) off[t * 16 + k] = excl + vals[k];
    if (t == 1023) off[B_BAGS] = sh[1023];
}

// ---------------------------------------------------------------------------
// Pooling kernel: warp per (bag, table). 8 warps / block.
// Grid is table-major: blocks [0,2048) -> table0, [2048,4096) -> table1, etc.
// so every warp in a block takes the same branch (uniform I-stream).
// Output layout: [B, 288] with column bases {0, 64, 192, 224}.
// ---------------------------------------------------------------------------
__global__ __launch_bounds__(256)
void pool_kernel(const float* __restrict__ W0, const float* __restrict__ W1,
                 const float* __restrict__ W2, const float* __restrict__ W3,
                 const int* __restrict__ ids0, const int* __restrict__ ids1,
                 const int* __restrict__ ids2, const int* __restrict__ ids3,
                 float* __restrict__ out) {
    int table = blockIdx.x >> 11;              // 2048 blocks per table
    int bag   = ((blockIdx.x & 2047) << 3) + (threadIdx.x >> 5);
    int lane  = threadIdx.x & 31;

    const int* off = g_off[table];
    int s = off[bag];
    int e = off[bag + 1];
    float* o = out + (size_t)bag * 288;

    if (table == 0 || table == 3) {
        // dim 64: float2 per lane (256B per row, fully coalesced)
        const float* W   = (table == 0) ? W0 : W3;
        const int*   ids = (table == 0) ? ids0 : ids3;
        int cb = (table == 0) ? 0 : 224;
        float2 acc = make_float2(0.f, 0.f);
        int j = s;
        for (; j + 4 <= e; j += 4) {
            int i0 = ids[j], i1 = ids[j + 1], i2 = ids[j + 2], i3 = ids[j + 3];
            float2 a = ((const float2*)(W + (size_t)i0 * 64))[lane];
            float2 b = ((const float2*)(W + (size_t)i1 * 64))[lane];
            float2 c = ((const float2*)(W + (size_t)i2 * 64))[lane];
            float2 d = ((const float2*)(W + (size_t)i3 * 64))[lane];
            acc.x += (a.x + b.x) + (c.x + d.x);
            acc.y += (a.y + b.y) + (c.y + d.y);
        }
        for (; j < e; j++) {
            float2 a = ((const float2*)(W + (size_t)ids[j] * 64))[lane];
            acc.x += a.x; acc.y += a.y;
        }
        ((float2*)(o + cb))[lane] = acc;
    } else if (table == 1) {
        // dim 128: float4 per lane (512B per row)
        float4 acc = make_float4(0.f, 0.f, 0.f, 0.f);
        int j = s;
        for (; j + 4 <= e; j += 4) {
            int i0 = ids1[j], i1 = ids1[j + 1], i2 = ids1[j + 2], i3 = ids1[j + 3];
            float4 a = ((const float4*)(W1 + (size_t)i0 * 128))[lane];
            float4 b = ((const float4*)(W1 + (size_t)i1 * 128))[lane];
            float4 c = ((const float4*)(W1 + (size_t)i2 * 128))[lane];
            float4 d = ((const float4*)(W1 + (size_t)i3 * 128))[lane];
            acc.x += (a.x + b.x) + (c.x + d.x);
            acc.y += (a.y + b.y) + (c.y + d.y);
            acc.z += (a.z + b.z) + (c.z + d.z);
            acc.w += (a.w + b.w) + (c.w + d.w);
        }
        for (; j < e; j++) {
            float4 a = ((const float4*)(W1 + (size_t)ids1[j] * 128))[lane];
            acc.x += a.x; acc.y += a.y; acc.z += a.z; acc.w += a.w;
        }
        ((float4*)(o + 64))[lane] = acc;
    } else {
        // dim 32: 1 float per lane (128B per row)
        float acc = 0.f;
        int j = s;
        for (; j + 4 <= e; j += 4) {
            int i0 = ids2[j], i1 = ids2[j + 1], i2 = ids2[j + 2], i3 = ids2[j + 3];
            float a = W2[(size_t)i0 * 32 + lane];
            float b = W2[(size_t)i1 * 32 + lane];
            float c = W2[(size_t)i2 * 32 + lane];
            float d = W2[(size_t)i3 * 32 + lane];
            acc += (a + b) + (c + d);
        }
        for (; j < e; j++) acc += W2[(size_t)ids2[j] * 32 + lane];
        o[192 + lane] = acc;
    }
}

// ---------------------------------------------------------------------------
// kernel_launch: identify inputs by element count (order-robust), then launch.
// ---------------------------------------------------------------------------
extern "C" void kernel_launch(void* const* d_in, const int* in_sizes, int n_in,
                              void* d_out, int out_size) {
    const float *W0 = nullptr, *W1 = nullptr, *W2 = nullptr, *W3 = nullptr;
    const int *ids0 = nullptr, *ids1 = nullptr, *ids2 = nullptr, *ids3 = nullptr;
    const int *lens[4] = {nullptr, nullptr, nullptr, nullptr};
    int nlens = 0;
    bool seenW64 = false, seenIds819 = false;

    for (int i = 0; i < n_in; i++) {
        long long sz = in_sizes[i];
        void* p = d_in[i];
        if (sz == 64000000LL) {               // 1M x 64 (tables 0 and 3)
            if (!seenW64) { W0 = (const float*)p; seenW64 = true; }
            else          { W3 = (const float*)p; }
        } else if (sz == 12800000LL) {        // 100K x 128
            W1 = (const float*)p;
        } else if (sz == 16000000LL) {        // 500K x 32
            W2 = (const float*)p;
        } else if (sz == 819200LL) {          // ids for tables 0 and 3
            if (!seenIds819) { ids0 = (const int*)p; seenIds819 = true; }
            else             { ids3 = (const int*)p; }
        } else if (sz == 327680LL) {
            ids1 = (const int*)p;
        } else if (sz == 1638400LL) {
            ids2 = (const int*)p;
        } else if (sz == 16384LL) {
            if (nlens < 4) lens[nlens++] = (const int*)p;
        }
    }

    scan_kernel<<<4, 1024>>>(lens[0], lens[1], lens[2], lens[3]);
    pool_kernel<<<B_BAGS / 2, 256>>>(W0, W1, W2, W3,
                                     ids0, ids1, ids2, ids3,
                                     (float*)d_out);
}

// round 7
// speedup vs baseline: 1.0379x; 1.0379x over previous
#include <cuda_runtime.h>
#include <cstdint>

#define B_BAGS 16384

// Per-table exclusive prefix offsets (scratch, computed each launch).
__device__ int g_off[4][B_BAGS + 1];

// ---------------------------------------------------------------------------
// Scan kernel: one block per table, 1024 threads, 16 lens each, shfl-scan
// (2 barriers total instead of 20).
// ---------------------------------------------------------------------------
__global__ void scan_kernel(const int* __restrict__ l0, const int* __restrict__ l1,
                            const int* __restrict__ l2, const int* __restrict__ l3) {
    const int* lens = (blockIdx.x == 0) ? l0 : (blockIdx.x == 1) ? l1
                    : (blockIdx.x == 2) ? l2 : l3;
    int* off = g_off[blockIdx.x];
    __shared__ int warp_sums[32];

    int t    = threadIdx.x;
    int wid  = t >> 5;
    int lane = t & 31;

    // Load 16 lens as 4x int4 (lens + t*16 is 16-int aligned).
    int4 v0 = ((const int4*)lens)[t * 4 + 0];
    int4 v1 = ((const int4*)lens)[t * 4 + 1];
    int4 v2 = ((const int4*)lens)[t * 4 + 2];
    int4 v3 = ((const int4*)lens)[t * 4 + 3];
    int vals[16] = {v0.x, v0.y, v0.z, v0.w, v1.x, v1.y, v1.z, v1.w,
                    v2.x, v2.y, v2.z, v2.w, v3.x, v3.y, v3.z, v3.w};

    int s = 0;
    int pre[16];
#pragma unroll
    for (int k = 0; k < 16; k++) { pre[k] = s; s += vals[k]; }

    // Inclusive warp scan of per-thread sums.
    int incl = s;
#pragma unroll
    for (int d = 1; d < 32; d <<= 1) {
        int x = __shfl_up_sync(0xffffffffu, incl, d);
        if (lane >= d) incl += x;
    }
    if (lane == 31) warp_sums[wid] = incl;
    __syncthreads();

    // Warp 0 scans the 32 warp totals (exclusive).
    if (wid == 0) {
        int w = warp_sums[lane];
        int wincl = w;
#pragma unroll
        for (int d = 1; d < 32; d <<= 1) {
            int x = __shfl_up_sync(0xffffffffu, wincl, d);
            if (lane >= d) wincl += x;
        }
        warp_sums[lane] = wincl - w;   // exclusive base per warp
    }
    __syncthreads();

    int base = warp_sums[wid] + (incl - s);   // exclusive prefix for this thread
#pragma unroll
    for (int k = 0; k < 16; k++) off[t * 16 + k] = base + pre[k];
    if (t == 1023) off[B_BAGS] = base + s;
}

// ---------------------------------------------------------------------------
// Pooling kernel: warp per (bag, table), 8 warps/block, table-major grid.
// Unroll 8 for MLP; __ldcs streams the big dim-64 tables (protect L2 for
// W1/W2 which are L2-resident across graph replays); __stcs streams output.
// Output layout: [B, 288], column bases {0, 64, 192, 224}.
// ---------------------------------------------------------------------------
__global__ __launch_bounds__(256)
void pool_kernel(const float* __restrict__ W0, const float* __restrict__ W1,
                 const float* __restrict__ W2, const float* __restrict__ W3,
                 const int* __restrict__ ids0, const int* __restrict__ ids1,
                 const int* __restrict__ ids2, const int* __restrict__ ids3,
                 float* __restrict__ out) {
    int table = blockIdx.x >> 11;              // 2048 blocks per table
    int bag   = ((blockIdx.x & 2047) << 3) + (threadIdx.x >> 5);
    int lane  = threadIdx.x & 31;

    const int* off = g_off[table];
    int s = off[bag];
    int e = off[bag + 1];
    float* o = out + (size_t)bag * 288;

    if (table == 0 || table == 3) {
        // dim 64: float2 per lane (256B/row). Streamed (.cs) — tables are 256MB.
        const float* W   = (table == 0) ? W0 : W3;
        const int*   ids = (table == 0) ? ids0 : ids3;
        int cb = (table == 0) ? 0 : 224;
        float2 acc = make_float2(0.f, 0.f);
        int j = s;
        for (; j + 8 <= e; j += 8) {
            int idx[8];
#pragma unroll
            for (int k = 0; k < 8; k++) idx[k] = ids[j + k];
            float2 v[8];
#pragma unroll
            for (int k = 0; k < 8; k++)
                v[k] = __ldcs((const float2*)(W + (size_t)idx[k] * 64) + lane);
#pragma unroll
            for (int k = 0; k < 8; k++) { acc.x += v[k].x; acc.y += v[k].y; }
        }
        for (; j < e; j++) {
            float2 a = __ldcs((const float2*)(W + (size_t)ids[j] * 64) + lane);
            acc.x += a.x; acc.y += a.y;
        }
        __stcs((float2*)(o + cb) + lane, acc);
    } else if (table == 1) {
        // dim 128: float4 per lane (512B/row). W1 = 51MB, want L2-resident.
        float4 acc = make_float4(0.f, 0.f, 0.f, 0.f);
        int j = s;
        for (; j + 8 <= e; j += 8) {
            int idx[8];
#pragma unroll
            for (int k = 0; k < 8; k++) idx[k] = ids1[j + k];
            float4 v[8];
#pragma unroll
            for (int k = 0; k < 8; k++)
                v[k] = *((const float4*)(W1 + (size_t)idx[k] * 128) + lane);
#pragma unroll
            for (int k = 0; k < 8; k++) {
                acc.x += v[k].x; acc.y += v[k].y; acc.z += v[k].z; acc.w += v[k].w;
            }
        }
        for (; j < e; j++) {
            float4 a = *((const float4*)(W1 + (size_t)ids1[j] * 128) + lane);
            acc.x += a.x; acc.y += a.y; acc.z += a.z; acc.w += a.w;
        }
        __stcs((float4*)(o + 64) + lane, acc);
    } else {
        // dim 32: 1 float per lane (128B/row). W2 = 64MB, want L2-resident.
        float acc = 0.f;
        int j = s;
        for (; j + 8 <= e; j += 8) {
            int idx[8];
#pragma unroll
            for (int k = 0; k < 8; k++) idx[k] = ids2[j + k];
            float v[8];
#pragma unroll
            for (int k = 0; k < 8; k++) v[k] = W2[(size_t)idx[k] * 32 + lane];
#pragma unroll
            for (int k = 0; k < 8; k++) acc += v[k];
        }
        for (; j < e; j++) acc += W2[(size_t)ids2[j] * 32 + lane];
        __stcs(o + 192 + lane, acc);
    }
}

// ---------------------------------------------------------------------------
// kernel_launch: identify inputs by element count (order-robust), then launch.
// ---------------------------------------------------------------------------
extern "C" void kernel_launch(void* const* d_in, const int* in_sizes, int n_in,
                              void* d_out, int out_size) {
    const float *W0 = nullptr, *W1 = nullptr, *W2 = nullptr, *W3 = nullptr;
    const int *ids0 = nullptr, *ids1 = nullptr, *ids2 = nullptr, *ids3 = nullptr;
    const int *lens[4] = {nullptr, nullptr, nullptr, nullptr};
    int nlens = 0;
    bool seenW64 = false, seenIds819 = false;

    for (int i = 0; i < n_in; i++) {
        long long sz = in_sizes[i];
        void* p = d_in[i];
        if (sz == 64000000LL) {               // 1M x 64 (tables 0 and 3)
            if (!seenW64) { W0 = (const float*)p; seenW64 = true; }
            else          { W3 = (const float*)p; }
        } else if (sz == 12800000LL) {        // 100K x 128
            W1 = (const float*)p;
        } else if (sz == 16000000LL) {        // 500K x 32
            W2 = (const float*)p;
        } else if (sz == 819200LL) {          // ids for tables 0 and 3
            if (!seenIds819) { ids0 = (const int*)p; seenIds819 = true; }
            else             { ids3 = (const int*)p; }
        } else if (sz == 327680LL) {
            ids1 = (const int*)p;
        } else if (sz == 1638400LL) {
            ids2 = (const int*)p;
        } else if (sz == 16384LL) {
            if (nlens < 4) lens[nlens++] = (const int*)p;
        }
    }

    scan_kernel<<<4, 1024>>>(lens[0], lens[1], lens[2], lens[3]);
    pool_kernel<<<B_BAGS / 2, 256>>>(W0, W1, W2, W3,
                                     ids0, ids1, ids2, ids3,
                                     (float*)d_out);
}